// round 1
// baseline (speedup 1.0000x reference)
#include <cuda_runtime.h>
#include <math.h>

#define BB 16
#define DD 128
#define LC 2048
#define LQ 512
#define NEGF (-1e30f)

// ---- scratch (device globals; no allocation) ----
__device__ float g_S[(size_t)BB * LC * LQ];     // 64 MB raw scores
__device__ float g_A[(size_t)BB * LC * DD];     // A = S1 @ Qt
__device__ float g_Bm[(size_t)BB * LC * DD];    // Bmat
__device__ float g_V2[(size_t)BB * LQ * DD];    // S2^T @ Ct
__device__ float g_V2p[(size_t)4 * BB * LQ * DD];  // split-K partials
__device__ float g_sub0[BB * LC];
__device__ float g_sub1[BB * LQ];               // includes bias
__device__ float g_rmax[BB * LC], g_rinv[BB * LC];  // softmax over q (per row c)
__device__ float g_cmax[BB * LQ], g_cinv[BB * LQ];  // softmax over c (per col q)

// ============================================================
// K0: sub0[b,c] = sum_d C[b,d,c]*w4C[d]; sub1[b,q] = sum_d Q[b,d,q]*w4Q[d] + bias
// ============================================================
__global__ void k_sub(const float* __restrict__ C, const float* __restrict__ Q,
                      const float* __restrict__ w4C, const float* __restrict__ w4Q,
                      const float* __restrict__ bias) {
    int t = blockIdx.x * blockDim.x + threadIdx.x;
    const int totC = BB * LC;
    if (t < totC) {
        int b = t / LC, c = t % LC;
        const float* Cp = C + (size_t)b * DD * LC + c;
        float s = 0.f;
        #pragma unroll 8
        for (int d = 0; d < DD; d++) s += Cp[(size_t)d * LC] * w4C[d];
        g_sub0[t] = s;
    } else if (t < totC + BB * LQ) {
        int u = t - totC;
        int b = u / LQ, q = u % LQ;
        const float* Qp = Q + (size_t)b * DD * LQ + q;
        float s = bias[0];
        #pragma unroll 8
        for (int d = 0; d < DD; d++) s += Qp[(size_t)d * LQ] * w4Q[d];
        g_sub1[u] = s;
    }
}

// ============================================================
// K1: S[b,c,q] = sum_d (C[b,d,c]*w4mlu[d]) * Q[b,d,q] + sub0[c] + sub1[q]
// 128x128 tile, BK=32, 256 threads, 8x8 register tile
// ============================================================
__global__ __launch_bounds__(256, 2) void k_scores(const float* __restrict__ C,
                                                   const float* __restrict__ Q,
                                                   const float* __restrict__ w4mlu) {
    __shared__ float Cs[32][128];
    __shared__ float Qs[32][128];
    int b = blockIdx.z;
    int cbase = blockIdx.y * 128;
    int qbase = blockIdx.x * 128;
    const float* Cb = C + (size_t)b * DD * LC + cbase;
    const float* Qb = Q + (size_t)b * DD * LQ + qbase;
    int tid = threadIdx.x;
    int tx = tid & 15, ty = tid >> 4;

    float acc[8][8];
    #pragma unroll
    for (int i = 0; i < 8; i++)
        #pragma unroll
        for (int j = 0; j < 8; j++) acc[i][j] = 0.f;

    for (int k0 = 0; k0 < DD; k0 += 32) {
        #pragma unroll
        for (int p = 0; p < 4; p++) {
            int r  = (tid >> 5) + p * 8;
            int c4 = (tid & 31) * 4;
            float w = w4mlu[k0 + r];
            float4 cv = *(const float4*)(Cb + (size_t)(k0 + r) * LC + c4);
            cv.x *= w; cv.y *= w; cv.z *= w; cv.w *= w;
            *(float4*)&Cs[r][c4] = cv;
            float4 qv = *(const float4*)(Qb + (size_t)(k0 + r) * LQ + c4);
            *(float4*)&Qs[r][c4] = qv;
        }
        __syncthreads();
        #pragma unroll
        for (int kk = 0; kk < 32; kk++) {
            float a[8], bv[8];
            float4 t0 = *(const float4*)&Cs[kk][ty * 4];
            float4 t1 = *(const float4*)&Cs[kk][64 + ty * 4];
            float4 u0 = *(const float4*)&Qs[kk][tx * 4];
            float4 u1 = *(const float4*)&Qs[kk][64 + tx * 4];
            a[0]=t0.x; a[1]=t0.y; a[2]=t0.z; a[3]=t0.w;
            a[4]=t1.x; a[5]=t1.y; a[6]=t1.z; a[7]=t1.w;
            bv[0]=u0.x; bv[1]=u0.y; bv[2]=u0.z; bv[3]=u0.w;
            bv[4]=u1.x; bv[5]=u1.y; bv[6]=u1.z; bv[7]=u1.w;
            #pragma unroll
            for (int i = 0; i < 8; i++)
                #pragma unroll
                for (int j = 0; j < 8; j++) acc[i][j] += a[i] * bv[j];
        }
        __syncthreads();
    }

    // epilogue: add sub0 + sub1, store S
    float s1v[8];
    #pragma unroll
    for (int j = 0; j < 8; j++) {
        int cc = (j < 4) ? tx * 4 + j : 64 + tx * 4 + (j - 4);
        s1v[j] = g_sub1[b * LQ + qbase + cc];
    }
    float* Sout = g_S + ((size_t)b * LC + cbase) * LQ + qbase;
    #pragma unroll
    for (int i = 0; i < 8; i++) {
        int r = (i < 4) ? ty * 4 + i : 64 + ty * 4 + (i - 4);
        float s0 = g_sub0[b * LC + cbase + r];
        float4 o0, o1;
        o0.x = acc[i][0] + s0 + s1v[0];
        o0.y = acc[i][1] + s0 + s1v[1];
        o0.z = acc[i][2] + s0 + s1v[2];
        o0.w = acc[i][3] + s0 + s1v[3];
        o1.x = acc[i][4] + s0 + s1v[4];
        o1.y = acc[i][5] + s0 + s1v[5];
        o1.z = acc[i][6] + s0 + s1v[6];
        o1.w = acc[i][7] + s0 + s1v[7];
        *(float4*)(Sout + (size_t)r * LQ + tx * 4)      = o0;
        *(float4*)(Sout + (size_t)r * LQ + 64 + tx * 4) = o1;
    }
}

// ============================================================
// K2a: softmax-over-q stats (one warp per (b,c) row of 512)
// ============================================================
__global__ void k_rowstats(const int* __restrict__ Qmask) {
    int w = blockIdx.x * 8 + (threadIdx.x >> 5);
    int lane = threadIdx.x & 31;
    if (w >= BB * LC) return;
    int b = w / LC;
    const float* Sp = g_S + (size_t)w * LQ;
    const int* qm = Qmask + b * LQ;
    float vals[16];
    float m = -INFINITY;
    #pragma unroll
    for (int i = 0; i < 16; i++) {
        int q = lane + 32 * i;
        float v = Sp[q];
        if (!qm[q]) v = NEGF;
        vals[i] = v;
        m = fmaxf(m, v);
    }
    #pragma unroll
    for (int o = 16; o > 0; o >>= 1) m = fmaxf(m, __shfl_xor_sync(0xffffffffu, m, o));
    float s = 0.f;
    #pragma unroll
    for (int i = 0; i < 16; i++) s += __expf(vals[i] - m);
    #pragma unroll
    for (int o = 16; o > 0; o >>= 1) s += __shfl_xor_sync(0xffffffffu, s, o);
    if (lane == 0) { g_rmax[w] = m; g_rinv[w] = 1.f / s; }
}

// ============================================================
// K2b: softmax-over-c stats (block = 32 q-columns x 8 c-strides, online)
// ============================================================
__global__ void k_colstats(const int* __restrict__ Cmask) {
    __shared__ float sm[8][33], ss[8][33];
    int b = blockIdx.y;
    int lane = threadIdx.x & 31;
    int yg = threadIdx.x >> 5;
    int q = blockIdx.x * 32 + lane;
    const float* Sp = g_S + (size_t)b * LC * LQ + q;
    const int* cmp = Cmask + b * LC;
    float m = -INFINITY, s = 0.f;
    for (int c = yg; c < LC; c += 8) {
        float v = Sp[(size_t)c * LQ];
        if (!cmp[c]) v = NEGF;
        float mn = fmaxf(m, v);
        s = s * __expf(m - mn) + __expf(v - mn);
        m = mn;
    }
    sm[yg][lane] = m; ss[yg][lane] = s;
    __syncthreads();
    if (yg == 0) {
        float M = m, S = s;
        #pragma unroll
        for (int g = 1; g < 8; g++) {
            float m2 = sm[g][lane], s2 = ss[g][lane];
            float mn = fmaxf(M, m2);
            S = S * __expf(M - mn) + s2 * __expf(m2 - mn);
            M = mn;
        }
        g_cmax[b * LQ + q] = M;
        g_cinv[b * LQ + q] = 1.f / S;
    }
}

// ============================================================
// K3: A[b,c,d] = sum_q S1[c,q] * Q[b,d,q]   (exp applied at smem fill)
// ============================================================
__global__ __launch_bounds__(256, 2) void k_gemmA(const float* __restrict__ Q,
                                                  const int* __restrict__ Qmask) {
    __shared__ float Ss[32][132];
    __shared__ float Qs[32][132];
    __shared__ float rmaxs[128], rinvs[128];
    __shared__ float qmadd[LQ];
    int b = blockIdx.y;
    int cbase = blockIdx.x * 128;
    int tid = threadIdx.x;
    if (tid < 128) {
        rmaxs[tid] = g_rmax[b * LC + cbase + tid];
        rinvs[tid] = g_rinv[b * LC + cbase + tid];
    }
    for (int i = tid; i < LQ; i += 256) qmadd[i] = Qmask[b * LQ + i] ? 0.f : NEGF;
    __syncthreads();
    int tx = tid & 15, ty = tid >> 4;
    float acc[8][8];
    #pragma unroll
    for (int i = 0; i < 8; i++)
        #pragma unroll
        for (int j = 0; j < 8; j++) acc[i][j] = 0.f;

    const float* Qb = Q + (size_t)b * DD * LQ;
    const float* Sb = g_S + ((size_t)b * LC + cbase) * LQ;

    for (int k0 = 0; k0 < LQ; k0 += 32) {
        #pragma unroll
        for (int p = 0; p < 4; p++) {
            int row = (tid >> 3) + p * 32;
            int qq  = (tid & 7) * 4;
            float4 v = *(const float4*)(Sb + (size_t)row * LQ + k0 + qq);
            float rm = rmaxs[row], ri = rinvs[row];
            Ss[qq + 0][row] = __expf(v.x + qmadd[k0 + qq + 0] - rm) * ri;
            Ss[qq + 1][row] = __expf(v.y + qmadd[k0 + qq + 1] - rm) * ri;
            Ss[qq + 2][row] = __expf(v.z + qmadd[k0 + qq + 2] - rm) * ri;
            Ss[qq + 3][row] = __expf(v.w + qmadd[k0 + qq + 3] - rm) * ri;
            float4 w = *(const float4*)(Qb + (size_t)row * LQ + k0 + qq);  // row = d
            Qs[qq + 0][row] = w.x; Qs[qq + 1][row] = w.y;
            Qs[qq + 2][row] = w.z; Qs[qq + 3][row] = w.w;
        }
        __syncthreads();
        #pragma unroll
        for (int kk = 0; kk < 32; kk++) {
            float a[8], bv[8];
            float4 t0 = *(const float4*)&Ss[kk][ty * 4];
            float4 t1 = *(const float4*)&Ss[kk][64 + ty * 4];
            float4 u0 = *(const float4*)&Qs[kk][tx * 4];
            float4 u1 = *(const float4*)&Qs[kk][64 + tx * 4];
            a[0]=t0.x; a[1]=t0.y; a[2]=t0.z; a[3]=t0.w;
            a[4]=t1.x; a[5]=t1.y; a[6]=t1.z; a[7]=t1.w;
            bv[0]=u0.x; bv[1]=u0.y; bv[2]=u0.z; bv[3]=u0.w;
            bv[4]=u1.x; bv[5]=u1.y; bv[6]=u1.z; bv[7]=u1.w;
            #pragma unroll
            for (int i = 0; i < 8; i++)
                #pragma unroll
                for (int j = 0; j < 8; j++) acc[i][j] += a[i] * bv[j];
        }
        __syncthreads();
    }

    float* Ab = g_A + ((size_t)b * LC + cbase) * DD;
    #pragma unroll
    for (int i = 0; i < 8; i++) {
        int r = (i < 4) ? ty * 4 + i : 64 + ty * 4 + (i - 4);
        float4 o0 = make_float4(acc[i][0], acc[i][1], acc[i][2], acc[i][3]);
        float4 o1 = make_float4(acc[i][4], acc[i][5], acc[i][6], acc[i][7]);
        *(float4*)(Ab + (size_t)r * DD + tx * 4)      = o0;
        *(float4*)(Ab + (size_t)r * DD + 64 + tx * 4) = o1;
    }
}

// ============================================================
// K4: V2 partials: V2[b,q,d] = sum_c S2[c,q]*C[b,d,c]; split-K over c (4 chunks)
// ============================================================
__global__ __launch_bounds__(256, 2) void k_gemmV2(const float* __restrict__ C,
                                                   const int* __restrict__ Cmask) {
    __shared__ float Ss[32][132];
    __shared__ float Cs[32][132];
    __shared__ float cmaxs[128], cinvs[128];
    __shared__ float cmadd[512];
    int b = blockIdx.z;
    int qbase = blockIdx.x * 128;
    int c0chunk = blockIdx.y * 512;
    int tid = threadIdx.x;
    if (tid < 128) {
        cmaxs[tid] = g_cmax[b * LQ + qbase + tid];
        cinvs[tid] = g_cinv[b * LQ + qbase + tid];
    }
    for (int i = tid; i < 512; i += 256) cmadd[i] = Cmask[b * LC + c0chunk + i] ? 0.f : NEGF;
    __syncthreads();
    int tx = tid & 15, ty = tid >> 4;
    float acc[8][8];
    #pragma unroll
    for (int i = 0; i < 8; i++)
        #pragma unroll
        for (int j = 0; j < 8; j++) acc[i][j] = 0.f;

    const float* Cb = C + (size_t)b * DD * LC;
    const float* Sb = g_S + ((size_t)b * LC + c0chunk) * LQ + qbase;

    for (int k0 = 0; k0 < 512; k0 += 32) {
        #pragma unroll
        for (int p = 0; p < 4; p++) {
            // S tile: rows kk (c), cols q contiguous (no transpose)
            int kk = (tid >> 5) + p * 8;
            int q4 = (tid & 31) * 4;
            float4 v = *(const float4*)(Sb + (size_t)(k0 + kk) * LQ + q4);
            float ca = cmadd[k0 + kk];
            float4 e;
            e.x = __expf(v.x + ca - cmaxs[q4 + 0]) * cinvs[q4 + 0];
            e.y = __expf(v.y + ca - cmaxs[q4 + 1]) * cinvs[q4 + 1];
            e.z = __expf(v.z + ca - cmaxs[q4 + 2]) * cinvs[q4 + 2];
            e.w = __expf(v.w + ca - cmaxs[q4 + 3]) * cinvs[q4 + 3];
            *(float4*)&Ss[kk][q4] = e;
            // C tile: rows d, cols kk (c), transpose into k-major
            int drow = (tid >> 3) + p * 32;
            int cc   = (tid & 7) * 4;
            float4 w = *(const float4*)(Cb + (size_t)drow * LC + c0chunk + k0 + cc);
            Cs[cc + 0][drow] = w.x; Cs[cc + 1][drow] = w.y;
            Cs[cc + 2][drow] = w.z; Cs[cc + 3][drow] = w.w;
        }
        __syncthreads();
        #pragma unroll
        for (int kk = 0; kk < 32; kk++) {
            float a[8], bv[8];
            float4 t0 = *(const float4*)&Ss[kk][ty * 4];
            float4 t1 = *(const float4*)&Ss[kk][64 + ty * 4];
            float4 u0 = *(const float4*)&Cs[kk][tx * 4];
            float4 u1 = *(const float4*)&Cs[kk][64 + tx * 4];
            a[0]=t0.x; a[1]=t0.y; a[2]=t0.z; a[3]=t0.w;
            a[4]=t1.x; a[5]=t1.y; a[6]=t1.z; a[7]=t1.w;
            bv[0]=u0.x; bv[1]=u0.y; bv[2]=u0.z; bv[3]=u0.w;
            bv[4]=u1.x; bv[5]=u1.y; bv[6]=u1.z; bv[7]=u1.w;
            #pragma unroll
            for (int i = 0; i < 8; i++)
                #pragma unroll
                for (int j = 0; j < 8; j++) acc[i][j] += a[i] * bv[j];
        }
        __syncthreads();
    }

    float* Vp = g_V2p + ((size_t)blockIdx.y * BB * LQ + (size_t)b * LQ + qbase) * DD;
    #pragma unroll
    for (int i = 0; i < 8; i++) {
        int r = (i < 4) ? ty * 4 + i : 64 + ty * 4 + (i - 4);
        float4 o0 = make_float4(acc[i][0], acc[i][1], acc[i][2], acc[i][3]);
        float4 o1 = make_float4(acc[i][4], acc[i][5], acc[i][6], acc[i][7]);
        *(float4*)(Vp + (size_t)r * DD + tx * 4)      = o0;
        *(float4*)(Vp + (size_t)r * DD + 64 + tx * 4) = o1;
    }
}

__global__ void k_reduceV2() {
    const int n = BB * LQ * DD / 4;
    int i = blockIdx.x * blockDim.x + threadIdx.x;
    if (i < n) {
        const float4* p = (const float4*)g_V2p;
        float4 a = p[i], b2 = p[i + n], c = p[i + 2 * n], d = p[i + 3 * n];
        float4 o;
        o.x = a.x + b2.x + c.x + d.x;
        o.y = a.y + b2.y + c.y + d.y;
        o.z = a.z + b2.z + c.z + d.z;
        o.w = a.w + b2.w + c.w + d.w;
        ((float4*)g_V2)[i] = o;
    }
}

// ============================================================
// K5: Bmat[b,c,d] = sum_q S1[c,q] * V2[b,q,d]
// ============================================================
__global__ __launch_bounds__(256, 2) void k_gemmB(const int* __restrict__ Qmask) {
    __shared__ float Ss[32][132];
    __shared__ float Vs[32][132];
    __shared__ float rmaxs[128], rinvs[128];
    __shared__ float qmadd[LQ];
    int b = blockIdx.y;
    int cbase = blockIdx.x * 128;
    int tid = threadIdx.x;
    if (tid < 128) {
        rmaxs[tid] = g_rmax[b * LC + cbase + tid];
        rinvs[tid] = g_rinv[b * LC + cbase + tid];
    }
    for (int i = tid; i < LQ; i += 256) qmadd[i] = Qmask[b * LQ + i] ? 0.f : NEGF;
    __syncthreads();
    int tx = tid & 15, ty = tid >> 4;
    float acc[8][8];
    #pragma unroll
    for (int i = 0; i < 8; i++)
        #pragma unroll
        for (int j = 0; j < 8; j++) acc[i][j] = 0.f;

    const float* Sb = g_S + ((size_t)b * LC + cbase) * LQ;
    const float* Vb = g_V2 + (size_t)b * LQ * DD;

    for (int k0 = 0; k0 < LQ; k0 += 32) {
        #pragma unroll
        for (int p = 0; p < 4; p++) {
            int row = (tid >> 3) + p * 32;
            int qq  = (tid & 7) * 4;
            float4 v = *(const float4*)(Sb + (size_t)row * LQ + k0 + qq);
            float rm = rmaxs[row], ri = rinvs[row];
            Ss[qq + 0][row] = __expf(v.x + qmadd[k0 + qq + 0] - rm) * ri;
            Ss[qq + 1][row] = __expf(v.y + qmadd[k0 + qq + 1] - rm) * ri;
            Ss[qq + 2][row] = __expf(v.z + qmadd[k0 + qq + 2] - rm) * ri;
            Ss[qq + 3][row] = __expf(v.w + qmadd[k0 + qq + 3] - rm) * ri;
            // V tile: rows kk (q), d contiguous (no transpose)
            int kk = (tid >> 5) + p * 8;
            int d4 = (tid & 31) * 4;
            float4 w = *(const float4*)(Vb + (size_t)(k0 + kk) * DD + d4);
            *(float4*)&Vs[kk][d4] = w;
        }
        __syncthreads();
        #pragma unroll
        for (int kk = 0; kk < 32; kk++) {
            float a[8], bv[8];
            float4 t0 = *(const float4*)&Ss[kk][ty * 4];
            float4 t1 = *(const float4*)&Ss[kk][64 + ty * 4];
            float4 u0 = *(const float4*)&Vs[kk][tx * 4];
            float4 u1 = *(const float4*)&Vs[kk][64 + tx * 4];
            a[0]=t0.x; a[1]=t0.y; a[2]=t0.z; a[3]=t0.w;
            a[4]=t1.x; a[5]=t1.y; a[6]=t1.z; a[7]=t1.w;
            bv[0]=u0.x; bv[1]=u0.y; bv[2]=u0.z; bv[3]=u0.w;
            bv[4]=u1.x; bv[5]=u1.y; bv[6]=u1.z; bv[7]=u1.w;
            #pragma unroll
            for (int i = 0; i < 8; i++)
                #pragma unroll
                for (int j = 0; j < 8; j++) acc[i][j] += a[i] * bv[j];
        }
        __syncthreads();
    }

    float* Bmb = g_Bm + ((size_t)b * LC + cbase) * DD;
    #pragma unroll
    for (int i = 0; i < 8; i++) {
        int r = (i < 4) ? ty * 4 + i : 64 + ty * 4 + (i - 4);
        float4 o0 = make_float4(acc[i][0], acc[i][1], acc[i][2], acc[i][3]);
        float4 o1 = make_float4(acc[i][4], acc[i][5], acc[i][6], acc[i][7]);
        *(float4*)(Bmb + (size_t)r * DD + tx * 4)      = o0;
        *(float4*)(Bmb + (size_t)r * DD + 64 + tx * 4) = o1;
    }
}

// ============================================================
// K6: assemble out[b, 4D, Lc] = concat(Ct, A, Ct*A, Ct*Bmat) transposed
// ============================================================
__global__ void k_assemble(const float* __restrict__ C, float* __restrict__ out) {
    __shared__ float As[32][33], Bs[32][33];
    int b = blockIdx.z;
    int cbase = blockIdx.x * 32;
    int dbase = blockIdx.y * 32;
    int x = threadIdx.x, y = threadIdx.y;  // (32, 8)
    #pragma unroll
    for (int yy = 0; yy < 4; yy++) {
        int c = y + 8 * yy;
        As[c][x] = g_A[((size_t)b * LC + cbase + c) * DD + dbase + x];
        Bs[c][x] = g_Bm[((size_t)b * LC + cbase + c) * DD + dbase + x];
    }
    __syncthreads();
    #pragma unroll
    for (int yy = 0; yy < 4; yy++) {
        int d = y + 8 * yy;
        float cv = C[((size_t)b * DD + dbase + d) * LC + cbase + x];
        float av = As[x][d];
        float bv = Bs[x][d];
        size_t obase = (size_t)b * 4 * DD * LC + cbase + x;
        out[obase + (size_t)(dbase + d) * LC]            = cv;
        out[obase + (size_t)(DD + dbase + d) * LC]       = av;
        out[obase + (size_t)(2 * DD + dbase + d) * LC]   = cv * av;
        out[obase + (size_t)(3 * DD + dbase + d) * LC]   = cv * bv;
    }
}

// ============================================================
extern "C" void kernel_launch(void* const* d_in, const int* in_sizes, int n_in,
                              void* d_out, int out_size) {
    const float* C     = (const float*)d_in[0];
    const float* Q     = (const float*)d_in[1];
    const int*   Cmask = (const int*)d_in[2];
    const int*   Qmask = (const int*)d_in[3];
    const float* w4C   = (const float*)d_in[4];
    const float* w4Q   = (const float*)d_in[5];
    const float* w4mlu = (const float*)d_in[6];
    const float* bias  = (const float*)d_in[7];
    float* out = (float*)d_out;

    int nsub = BB * LC + BB * LQ;
    k_sub<<<(nsub + 255) / 256, 256>>>(C, Q, w4C, w4Q, bias);
    k_scores<<<dim3(4, 16, 16), 256>>>(C, Q, w4mlu);
    k_rowstats<<<(BB * LC) / 8, 256>>>(Qmask);
    k_colstats<<<dim3(16, 16), 256>>>(Cmask);
    k_gemmA<<<dim3(16, 16), 256>>>(Q, Qmask);
    k_gemmV2<<<dim3(4, 4, 16), 256>>>(C, Cmask);
    k_reduceV2<<<(BB * LQ * DD / 4 + 255) / 256, 256>>>();
    k_gemmB<<<dim3(16, 16), 256>>>(Qmask);
    k_assemble<<<dim3(64, 4, 16), dim3(32, 8)>>>(C, out);
}

// round 2
// speedup vs baseline: 1.1190x; 1.1190x over previous
#include <cuda_runtime.h>
#include <math.h>

#define BB 16
#define DD 128
#define LC 2048
#define LQ 512
#define NEGF (-1e30f)

// ---- scratch (device globals; no allocation) ----
__device__ float g_S[(size_t)BB * LC * LQ];     // 64 MB raw scores
__device__ float g_A[(size_t)BB * LC * DD];
__device__ float g_Bm[(size_t)BB * LC * DD];
__device__ float g_V2[(size_t)BB * LQ * DD];
__device__ float g_V2p[(size_t)4 * BB * LQ * DD];
__device__ float g_sub0[BB * LC];
__device__ float g_sub1[BB * LQ];
__device__ float g_rmax[BB * LC], g_rinv[BB * LC];
__device__ float g_cmax[BB * LQ], g_cinv[BB * LQ];
__device__ float g_cpm[4 * BB * LQ], g_cps[4 * BB * LQ];  // colstats partials

// ---- f32x2 helpers ----
__device__ __forceinline__ unsigned long long rep2(float x) {
    unsigned long long r;
    asm("mov.b64 %0, {%1, %1};" : "=l"(r) : "f"(x));
    return r;
}
__device__ __forceinline__ float2 u2f(unsigned long long v) {
    float2 r;
    asm("mov.b64 {%0, %1}, %2;" : "=f"(r.x), "=f"(r.y) : "l"(v));
    return r;
}
#define FMA2(d, a, b) asm("fma.rn.f32x2 %0, %1, %2, %0;" : "+l"(d) : "l"(a), "l"(b))

// Microkernel: acc2[p][j] accumulates rows (pair p along i) x cols j.
// As_ rows provide the i-operand (pairs free via 8B smem loads),
// Bs_ rows provide the j-operand (replicated via mov.b64).
#define MK_INNER(As_, Bs_)                                                       \
    _Pragma("unroll")                                                            \
    for (int kk = 0; kk < 32; kk++) {                                            \
        const unsigned long long* apl = (const unsigned long long*)&As_[kk][ty * 4];      \
        const unsigned long long* aph = (const unsigned long long*)&As_[kk][64 + ty * 4]; \
        unsigned long long a2[4];                                                \
        a2[0] = apl[0]; a2[1] = apl[1]; a2[2] = aph[0]; a2[3] = aph[1];          \
        float4 u0 = *(const float4*)&Bs_[kk][tx * 4];                            \
        float4 u1 = *(const float4*)&Bs_[kk][64 + tx * 4];                       \
        unsigned long long bb[8];                                                \
        bb[0] = rep2(u0.x); bb[1] = rep2(u0.y); bb[2] = rep2(u0.z); bb[3] = rep2(u0.w); \
        bb[4] = rep2(u1.x); bb[5] = rep2(u1.y); bb[6] = rep2(u1.z); bb[7] = rep2(u1.w); \
        _Pragma("unroll")                                                        \
        for (int p = 0; p < 4; p++)                                              \
            _Pragma("unroll")                                                    \
            for (int j = 0; j < 8; j++) FMA2(acc2[p][j], a2[p], bb[j]);          \
    }

#define MK_UNPACK()                                                              \
    float accf[8][8];                                                            \
    _Pragma("unroll")                                                            \
    for (int p = 0; p < 4; p++)                                                  \
        _Pragma("unroll")                                                        \
        for (int j = 0; j < 8; j++) {                                            \
            float2 v = u2f(acc2[p][j]);                                          \
            accf[2 * p][j] = v.x; accf[2 * p + 1][j] = v.y;                      \
        }

// ============================================================
// K0: sub0 / sub1 reductions
// ============================================================
__global__ void k_sub(const float* __restrict__ C, const float* __restrict__ Q,
                      const float* __restrict__ w4C, const float* __restrict__ w4Q,
                      const float* __restrict__ bias) {
    int t = blockIdx.x * blockDim.x + threadIdx.x;
    const int totC = BB * LC;
    if (t < totC) {
        int b = t / LC, c = t % LC;
        const float* Cp = C + (size_t)b * DD * LC + c;
        float s = 0.f;
        #pragma unroll 8
        for (int d = 0; d < DD; d++) s += Cp[(size_t)d * LC] * w4C[d];
        g_sub0[t] = s;
    } else if (t < totC + BB * LQ) {
        int u = t - totC;
        int b = u / LQ, q = u % LQ;
        const float* Qp = Q + (size_t)b * DD * LQ + q;
        float s = bias[0];
        #pragma unroll 8
        for (int d = 0; d < DD; d++) s += Qp[(size_t)d * LQ] * w4Q[d];
        g_sub1[u] = s;
    }
}

// ============================================================
// K1: S = (C*w4mlu)^T Q + sub0 + sub1
// ============================================================
__global__ __launch_bounds__(256, 2) void k_scores(const float* __restrict__ C,
                                                   const float* __restrict__ Q,
                                                   const float* __restrict__ w4mlu) {
    __shared__ float Cs[32][128];
    __shared__ float Qs[32][128];
    int b = blockIdx.z;
    int cbase = blockIdx.y * 128;
    int qbase = blockIdx.x * 128;
    const float* Cb = C + (size_t)b * DD * LC + cbase;
    const float* Qb = Q + (size_t)b * DD * LQ + qbase;
    int tid = threadIdx.x;
    int tx = tid & 15, ty = tid >> 4;

    unsigned long long acc2[4][8];
    #pragma unroll
    for (int p = 0; p < 4; p++)
        #pragma unroll
        for (int j = 0; j < 8; j++) acc2[p][j] = 0ull;

    for (int k0 = 0; k0 < DD; k0 += 32) {
        #pragma unroll
        for (int p = 0; p < 4; p++) {
            int r  = (tid >> 5) + p * 8;
            int c4 = (tid & 31) * 4;
            float w = w4mlu[k0 + r];
            float4 cv = *(const float4*)(Cb + (size_t)(k0 + r) * LC + c4);
            cv.x *= w; cv.y *= w; cv.z *= w; cv.w *= w;
            *(float4*)&Cs[r][c4] = cv;
            float4 qv = *(const float4*)(Qb + (size_t)(k0 + r) * LQ + c4);
            *(float4*)&Qs[r][c4] = qv;
        }
        __syncthreads();
        MK_INNER(Cs, Qs)
        __syncthreads();
    }
    MK_UNPACK()

    float s1v[8];
    #pragma unroll
    for (int j = 0; j < 8; j++) {
        int cc = (j < 4) ? tx * 4 + j : 64 + tx * 4 + (j - 4);
        s1v[j] = g_sub1[b * LQ + qbase + cc];
    }
    float* Sout = g_S + ((size_t)b * LC + cbase) * LQ + qbase;
    #pragma unroll
    for (int i = 0; i < 8; i++) {
        int r = (i < 4) ? ty * 4 + i : 64 + ty * 4 + (i - 4);
        float s0 = g_sub0[b * LC + cbase + r];
        float4 o0, o1;
        o0.x = accf[i][0] + s0 + s1v[0];
        o0.y = accf[i][1] + s0 + s1v[1];
        o0.z = accf[i][2] + s0 + s1v[2];
        o0.w = accf[i][3] + s0 + s1v[3];
        o1.x = accf[i][4] + s0 + s1v[4];
        o1.y = accf[i][5] + s0 + s1v[5];
        o1.z = accf[i][6] + s0 + s1v[6];
        o1.w = accf[i][7] + s0 + s1v[7];
        *(float4*)(Sout + (size_t)r * LQ + tx * 4)      = o0;
        *(float4*)(Sout + (size_t)r * LQ + 64 + tx * 4) = o1;
    }
}

// ============================================================
// K2a: softmax-over-q stats (one warp per (b,c) row)
// ============================================================
__global__ void k_rowstats(const int* __restrict__ Qmask) {
    int w = blockIdx.x * 8 + (threadIdx.x >> 5);
    int lane = threadIdx.x & 31;
    if (w >= BB * LC) return;
    int b = w / LC;
    const float* Sp = g_S + (size_t)w * LQ;
    const int* qm = Qmask + b * LQ;
    float vals[16];
    float m = -INFINITY;
    #pragma unroll
    for (int i = 0; i < 16; i++) {
        int q = lane + 32 * i;
        float v = Sp[q];
        if (!qm[q]) v += NEGF;
        vals[i] = v;
        m = fmaxf(m, v);
    }
    #pragma unroll
    for (int o = 16; o > 0; o >>= 1) m = fmaxf(m, __shfl_xor_sync(0xffffffffu, m, o));
    float s = 0.f;
    #pragma unroll
    for (int i = 0; i < 16; i++) s += __expf(vals[i] - m);
    #pragma unroll
    for (int o = 16; o > 0; o >>= 1) s += __shfl_xor_sync(0xffffffffu, s, o);
    if (lane == 0) { g_rmax[w] = m; g_rinv[w] = 1.f / s; }
}

// ============================================================
// K2b: softmax-over-c partial stats (c split into 4 chunks, MLP=4)
// ============================================================
__global__ void k_colstats_part(const int* __restrict__ Cmask) {
    __shared__ float sm[8][33], ss[8][33];
    __shared__ float cadd[512];
    int b = blockIdx.z;
    int chunk = blockIdx.y * 512;
    int lane = threadIdx.x & 31;
    int yg = threadIdx.x >> 5;
    for (int i = threadIdx.x; i < 512; i += 256)
        cadd[i] = Cmask[b * LC + chunk + i] ? 0.f : NEGF;
    __syncthreads();
    int q = blockIdx.x * 32 + lane;
    int cloc = yg * 64;
    const float* Sp = g_S + (size_t)b * LC * LQ + (size_t)(chunk + cloc) * LQ + q;
    float m = -INFINITY, s = 0.f;
    #pragma unroll 4
    for (int i = 0; i < 16; i++) {
        const float* p = Sp + (size_t)i * 4 * LQ;
        float v0 = p[0]          + cadd[cloc + i * 4 + 0];
        float v1 = p[LQ]         + cadd[cloc + i * 4 + 1];
        float v2 = p[2 * LQ]     + cadd[cloc + i * 4 + 2];
        float v3 = p[3 * LQ]     + cadd[cloc + i * 4 + 3];
        float m4 = fmaxf(fmaxf(v0, v1), fmaxf(v2, v3));
        float mn = fmaxf(m, m4);
        s = s * __expf(m - mn) + __expf(v0 - mn) + __expf(v1 - mn)
                               + __expf(v2 - mn) + __expf(v3 - mn);
        m = mn;
    }
    sm[yg][lane] = m; ss[yg][lane] = s;
    __syncthreads();
    if (yg == 0) {
        float M = m, S = s;
        #pragma unroll
        for (int g = 1; g < 8; g++) {
            float m2 = sm[g][lane], s2 = ss[g][lane];
            float mn = fmaxf(M, m2);
            S = S * __expf(M - mn) + s2 * __expf(m2 - mn);
            M = mn;
        }
        int idx = (blockIdx.y * BB + b) * LQ + q;
        g_cpm[idx] = M;
        g_cps[idx] = S;
    }
}

__global__ void k_colstats_merge() {
    int t = blockIdx.x * 256 + threadIdx.x;
    if (t >= BB * LQ) return;
    float M = -INFINITY, S = 0.f;
    #pragma unroll
    for (int g = 0; g < 4; g++) {
        float m2 = g_cpm[g * BB * LQ + t], s2 = g_cps[g * BB * LQ + t];
        float mn = fmaxf(M, m2);
        S = S * __expf(M - mn) + s2 * __expf(m2 - mn);
        M = mn;
    }
    g_cmax[t] = M;
    g_cinv[t] = 1.f / S;
}

// ============================================================
// K3: A = S1 @ Qt
// ============================================================
__global__ __launch_bounds__(256, 2) void k_gemmA(const float* __restrict__ Q,
                                                  const int* __restrict__ Qmask) {
    __shared__ float Ss[32][132];
    __shared__ float Qs[32][132];
    __shared__ float rmaxs[128], rinvs[128];
    __shared__ float qmadd[LQ];
    int b = blockIdx.y;
    int cbase = blockIdx.x * 128;
    int tid = threadIdx.x;
    if (tid < 128) {
        rmaxs[tid] = g_rmax[b * LC + cbase + tid];
        rinvs[tid] = g_rinv[b * LC + cbase + tid];
    }
    for (int i = tid; i < LQ; i += 256) qmadd[i] = Qmask[b * LQ + i] ? 0.f : NEGF;
    __syncthreads();
    int tx = tid & 15, ty = tid >> 4;
    unsigned long long acc2[4][8];
    #pragma unroll
    for (int p = 0; p < 4; p++)
        #pragma unroll
        for (int j = 0; j < 8; j++) acc2[p][j] = 0ull;

    const float* Qb = Q + (size_t)b * DD * LQ;
    const float* Sb = g_S + ((size_t)b * LC + cbase) * LQ;

    for (int k0 = 0; k0 < LQ; k0 += 32) {
        #pragma unroll
        for (int p = 0; p < 4; p++) {
            int row = (tid >> 3) + p * 32;
            int qq  = (tid & 7) * 4;
            float4 v = *(const float4*)(Sb + (size_t)row * LQ + k0 + qq);
            float rm = rmaxs[row], ri = rinvs[row];
            Ss[qq + 0][row] = __expf(v.x + qmadd[k0 + qq + 0] - rm) * ri;
            Ss[qq + 1][row] = __expf(v.y + qmadd[k0 + qq + 1] - rm) * ri;
            Ss[qq + 2][row] = __expf(v.z + qmadd[k0 + qq + 2] - rm) * ri;
            Ss[qq + 3][row] = __expf(v.w + qmadd[k0 + qq + 3] - rm) * ri;
            float4 w = *(const float4*)(Qb + (size_t)row * LQ + k0 + qq);
            Qs[qq + 0][row] = w.x; Qs[qq + 1][row] = w.y;
            Qs[qq + 2][row] = w.z; Qs[qq + 3][row] = w.w;
        }
        __syncthreads();
        MK_INNER(Ss, Qs)
        __syncthreads();
    }
    MK_UNPACK()

    float* Ab = g_A + ((size_t)b * LC + cbase) * DD;
    #pragma unroll
    for (int i = 0; i < 8; i++) {
        int r = (i < 4) ? ty * 4 + i : 64 + ty * 4 + (i - 4);
        float4 o0 = make_float4(accf[i][0], accf[i][1], accf[i][2], accf[i][3]);
        float4 o1 = make_float4(accf[i][4], accf[i][5], accf[i][6], accf[i][7]);
        *(float4*)(Ab + (size_t)r * DD + tx * 4)      = o0;
        *(float4*)(Ab + (size_t)r * DD + 64 + tx * 4) = o1;
    }
}

// ============================================================
// K4: V2 partials: V2[b,q,d] = sum_c S2[c,q]*C[b,d,c]
// ============================================================
__global__ __launch_bounds__(256, 2) void k_gemmV2(const float* __restrict__ C,
                                                   const int* __restrict__ Cmask) {
    __shared__ float Ss[32][132];
    __shared__ float Cs[32][132];
    __shared__ float cmaxs[128], cinvs[128];
    __shared__ float cmadd[512];
    int b = blockIdx.z;
    int qbase = blockIdx.x * 128;
    int c0chunk = blockIdx.y * 512;
    int tid = threadIdx.x;
    if (tid < 128) {
        cmaxs[tid] = g_cmax[b * LQ + qbase + tid];
        cinvs[tid] = g_cinv[b * LQ + qbase + tid];
    }
    for (int i = tid; i < 512; i += 256) cmadd[i] = Cmask[b * LC + c0chunk + i] ? 0.f : NEGF;
    __syncthreads();
    int tx = tid & 15, ty = tid >> 4;
    unsigned long long acc2[4][8];
    #pragma unroll
    for (int p = 0; p < 4; p++)
        #pragma unroll
        for (int j = 0; j < 8; j++) acc2[p][j] = 0ull;

    const float* Cb = C + (size_t)b * DD * LC;
    const float* Sb = g_S + ((size_t)b * LC + c0chunk) * LQ + qbase;

    for (int k0 = 0; k0 < 512; k0 += 32) {
        #pragma unroll
        for (int p = 0; p < 4; p++) {
            int kk = (tid >> 5) + p * 8;
            int q4 = (tid & 31) * 4;
            float4 v = *(const float4*)(Sb + (size_t)(k0 + kk) * LQ + q4);
            float ca = cmadd[k0 + kk];
            float4 e;
            e.x = __expf(v.x + ca - cmaxs[q4 + 0]) * cinvs[q4 + 0];
            e.y = __expf(v.y + ca - cmaxs[q4 + 1]) * cinvs[q4 + 1];
            e.z = __expf(v.z + ca - cmaxs[q4 + 2]) * cinvs[q4 + 2];
            e.w = __expf(v.w + ca - cmaxs[q4 + 3]) * cinvs[q4 + 3];
            *(float4*)&Ss[kk][q4] = e;
            int drow = (tid >> 3) + p * 32;
            int cc   = (tid & 7) * 4;
            float4 w = *(const float4*)(Cb + (size_t)drow * LC + c0chunk + k0 + cc);
            Cs[cc + 0][drow] = w.x; Cs[cc + 1][drow] = w.y;
            Cs[cc + 2][drow] = w.z; Cs[cc + 3][drow] = w.w;
        }
        __syncthreads();
        MK_INNER(Ss, Cs)
        __syncthreads();
    }
    MK_UNPACK()

    float* Vp = g_V2p + ((size_t)blockIdx.y * BB * LQ + (size_t)b * LQ + qbase) * DD;
    #pragma unroll
    for (int i = 0; i < 8; i++) {
        int r = (i < 4) ? ty * 4 + i : 64 + ty * 4 + (i - 4);
        float4 o0 = make_float4(accf[i][0], accf[i][1], accf[i][2], accf[i][3]);
        float4 o1 = make_float4(accf[i][4], accf[i][5], accf[i][6], accf[i][7]);
        *(float4*)(Vp + (size_t)r * DD + tx * 4)      = o0;
        *(float4*)(Vp + (size_t)r * DD + 64 + tx * 4) = o1;
    }
}

__global__ void k_reduceV2() {
    const int n = BB * LQ * DD / 4;
    int i = blockIdx.x * blockDim.x + threadIdx.x;
    if (i < n) {
        const float4* p = (const float4*)g_V2p;
        float4 a = p[i], b2 = p[i + n], c = p[i + 2 * n], d = p[i + 3 * n];
        float4 o;
        o.x = a.x + b2.x + c.x + d.x;
        o.y = a.y + b2.y + c.y + d.y;
        o.z = a.z + b2.z + c.z + d.z;
        o.w = a.w + b2.w + c.w + d.w;
        ((float4*)g_V2)[i] = o;
    }
}

// ============================================================
// K5: Bmat = S1 @ V2
// ============================================================
__global__ __launch_bounds__(256, 2) void k_gemmB(const int* __restrict__ Qmask) {
    __shared__ float Ss[32][132];
    __shared__ float Vs[32][132];
    __shared__ float rmaxs[128], rinvs[128];
    __shared__ float qmadd[LQ];
    int b = blockIdx.y;
    int cbase = blockIdx.x * 128;
    int tid = threadIdx.x;
    if (tid < 128) {
        rmaxs[tid] = g_rmax[b * LC + cbase + tid];
        rinvs[tid] = g_rinv[b * LC + cbase + tid];
    }
    for (int i = tid; i < LQ; i += 256) qmadd[i] = Qmask[b * LQ + i] ? 0.f : NEGF;
    __syncthreads();
    int tx = tid & 15, ty = tid >> 4;
    unsigned long long acc2[4][8];
    #pragma unroll
    for (int p = 0; p < 4; p++)
        #pragma unroll
        for (int j = 0; j < 8; j++) acc2[p][j] = 0ull;

    const float* Sb = g_S + ((size_t)b * LC + cbase) * LQ;
    const float* Vb = g_V2 + (size_t)b * LQ * DD;

    for (int k0 = 0; k0 < LQ; k0 += 32) {
        #pragma unroll
        for (int p = 0; p < 4; p++) {
            int row = (tid >> 3) + p * 32;
            int qq  = (tid & 7) * 4;
            float4 v = *(const float4*)(Sb + (size_t)row * LQ + k0 + qq);
            float rm = rmaxs[row], ri = rinvs[row];
            Ss[qq + 0][row] = __expf(v.x + qmadd[k0 + qq + 0] - rm) * ri;
            Ss[qq + 1][row] = __expf(v.y + qmadd[k0 + qq + 1] - rm) * ri;
            Ss[qq + 2][row] = __expf(v.z + qmadd[k0 + qq + 2] - rm) * ri;
            Ss[qq + 3][row] = __expf(v.w + qmadd[k0 + qq + 3] - rm) * ri;
            int kk = (tid >> 5) + p * 8;
            int d4 = (tid & 31) * 4;
            float4 w = *(const float4*)(Vb + (size_t)(k0 + kk) * DD + d4);
            *(float4*)&Vs[kk][d4] = w;
        }
        __syncthreads();
        MK_INNER(Ss, Vs)
        __syncthreads();
    }
    MK_UNPACK()

    float* Bmb = g_Bm + ((size_t)b * LC + cbase) * DD;
    #pragma unroll
    for (int i = 0; i < 8; i++) {
        int r = (i < 4) ? ty * 4 + i : 64 + ty * 4 + (i - 4);
        float4 o0 = make_float4(accf[i][0], accf[i][1], accf[i][2], accf[i][3]);
        float4 o1 = make_float4(accf[i][4], accf[i][5], accf[i][6], accf[i][7]);
        *(float4*)(Bmb + (size_t)r * DD + tx * 4)      = o0;
        *(float4*)(Bmb + (size_t)r * DD + 64 + tx * 4) = o1;
    }
}

// ============================================================
// K6: assemble out[b, 4D, Lc]
// ============================================================
__global__ void k_assemble(const float* __restrict__ C, float* __restrict__ out) {
    __shared__ float As[32][33], Bs[32][33];
    int b = blockIdx.z;
    int cbase = blockIdx.x * 32;
    int dbase = blockIdx.y * 32;
    int x = threadIdx.x, y = threadIdx.y;
    #pragma unroll
    for (int yy = 0; yy < 4; yy++) {
        int c = y + 8 * yy;
        As[c][x] = g_A[((size_t)b * LC + cbase + c) * DD + dbase + x];
        Bs[c][x] = g_Bm[((size_t)b * LC + cbase + c) * DD + dbase + x];
    }
    __syncthreads();
    #pragma unroll
    for (int yy = 0; yy < 4; yy++) {
        int d = y + 8 * yy;
        float cv = C[((size_t)b * DD + dbase + d) * LC + cbase + x];
        float av = As[x][d];
        float bv = Bs[x][d];
        size_t obase = (size_t)b * 4 * DD * LC + cbase + x;
        out[obase + (size_t)(dbase + d) * LC]            = cv;
        out[obase + (size_t)(DD + dbase + d) * LC]       = av;
        out[obase + (size_t)(2 * DD + dbase + d) * LC]   = cv * av;
        out[obase + (size_t)(3 * DD + dbase + d) * LC]   = cv * bv;
    }
}

// ============================================================
extern "C" void kernel_launch(void* const* d_in, const int* in_sizes, int n_in,
                              void* d_out, int out_size) {
    const float* C     = (const float*)d_in[0];
    const float* Q     = (const float*)d_in[1];
    const int*   Cmask = (const int*)d_in[2];
    const int*   Qmask = (const int*)d_in[3];
    const float* w4C   = (const float*)d_in[4];
    const float* w4Q   = (const float*)d_in[5];
    const float* w4mlu = (const float*)d_in[6];
    const float* bias  = (const float*)d_in[7];
    float* out = (float*)d_out;

    int nsub = BB * LC + BB * LQ;
    k_sub<<<(nsub + 255) / 256, 256>>>(C, Q, w4C, w4Q, bias);
    k_scores<<<dim3(4, 16, 16), 256>>>(C, Q, w4mlu);
    k_rowstats<<<(BB * LC) / 8, 256>>>(Qmask);
    k_colstats_part<<<dim3(16, 4, 16), 256>>>(Cmask);
    k_colstats_merge<<<32, 256>>>();
    k_gemmA<<<dim3(16, 16), 256>>>(Q, Qmask);
    k_gemmV2<<<dim3(4, 4, 16), 256>>>(C, Cmask);
    k_reduceV2<<<(BB * LQ * DD / 4 + 255) / 256, 256>>>();
    k_gemmB<<<dim3(16, 16), 256>>>(Qmask);
    k_assemble<<<dim3(64, 4, 16), dim3(32, 8)>>>(C, out);
}

// round 3
// speedup vs baseline: 1.1200x; 1.0009x over previous
#include <cuda_runtime.h>
#include <math.h>

#define BB 16
#define DD 128
#define LC 2048
#define LQ 512
#define NEGF (-1e30f)

// ---- scratch (device globals; no allocation) ----
__device__ float g_S[(size_t)BB * LC * LQ];     // 64 MB raw scores
__device__ float g_A[(size_t)BB * LC * DD];
__device__ float g_Bm[(size_t)BB * LC * DD];
__device__ float g_V2[(size_t)BB * LQ * DD];
__device__ float g_V2p[(size_t)4 * BB * LQ * DD];
__device__ float g_sub0[BB * LC];
__device__ float g_sub1[BB * LQ];
__device__ float g_rmax[BB * LC], g_rinv[BB * LC];
__device__ float g_cmax[BB * LQ], g_cinv[BB * LQ];
__device__ float g_cpm[4 * BB * LQ], g_cps[4 * BB * LQ];  // colstats partials

// ---- f32x2 helpers ----
__device__ __forceinline__ unsigned long long rep2(float x) {
    unsigned long long r;
    asm("mov.b64 %0, {%1, %1};" : "=l"(r) : "f"(x));
    return r;
}
__device__ __forceinline__ float2 u2f(unsigned long long v) {
    float2 r;
    asm("mov.b64 {%0, %1}, %2;" : "=f"(r.x), "=f"(r.y) : "l"(v));
    return r;
}
#define FMA2(d, a, b) asm("fma.rn.f32x2 %0, %1, %2, %0;" : "+l"(d) : "l"(a), "l"(b))

// Microkernel: acc2[p][j] accumulates rows (pair p along i) x cols j.
// As_ rows provide the i-operand (pairs free via 8B smem loads),
// Bs_ rows provide the j-operand (replicated via mov.b64).
#define MK_INNER(As_, Bs_)                                                       \
    _Pragma("unroll")                                                            \
    for (int kk = 0; kk < 32; kk++) {                                            \
        const unsigned long long* apl = (const unsigned long long*)&As_[kk][ty * 4];      \
        const unsigned long long* aph = (const unsigned long long*)&As_[kk][64 + ty * 4]; \
        unsigned long long a2[4];                                                \
        a2[0] = apl[0]; a2[1] = apl[1]; a2[2] = aph[0]; a2[3] = aph[1];          \
        float4 u0 = *(const float4*)&Bs_[kk][tx * 4];                            \
        float4 u1 = *(const float4*)&Bs_[kk][64 + tx * 4];                       \
        unsigned long long bb[8];                                                \
        bb[0] = rep2(u0.x); bb[1] = rep2(u0.y); bb[2] = rep2(u0.z); bb[3] = rep2(u0.w); \
        bb[4] = rep2(u1.x); bb[5] = rep2(u1.y); bb[6] = rep2(u1.z); bb[7] = rep2(u1.w); \
        _Pragma("unroll")                                                        \
        for (int p = 0; p < 4; p++)                                              \
            _Pragma("unroll")                                                    \
            for (int j = 0; j < 8; j++) FMA2(acc2[p][j], a2[p], bb[j]);          \
    }

#define MK_UNPACK()                                                              \
    float accf[8][8];                                                            \
    _Pragma("unroll")                                                            \
    for (int p = 0; p < 4; p++)                                                  \
        _Pragma("unroll")                                                        \
        for (int j = 0; j < 8; j++) {                                            \
            float2 v = u2f(acc2[p][j]);                                          \
            accf[2 * p][j] = v.x; accf[2 * p + 1][j] = v.y;                      \
        }

// ============================================================
// K0: sub0 / sub1 reductions
// ============================================================
__global__ void k_sub(const float* __restrict__ C, const float* __restrict__ Q,
                      const float* __restrict__ w4C, const float* __restrict__ w4Q,
                      const float* __restrict__ bias) {
    int t = blockIdx.x * blockDim.x + threadIdx.x;
    const int totC = BB * LC;
    if (t < totC) {
        int b = t / LC, c = t % LC;
        const float* Cp = C + (size_t)b * DD * LC + c;
        float s = 0.f;
        #pragma unroll 8
        for (int d = 0; d < DD; d++) s += Cp[(size_t)d * LC] * w4C[d];
        g_sub0[t] = s;
    } else if (t < totC + BB * LQ) {
        int u = t - totC;
        int b = u / LQ, q = u % LQ;
        const float* Qp = Q + (size_t)b * DD * LQ + q;
        float s = bias[0];
        #pragma unroll 8
        for (int d = 0; d < DD; d++) s += Qp[(size_t)d * LQ] * w4Q[d];
        g_sub1[u] = s;
    }
}

// ============================================================
// K1: S = (C*w4mlu)^T Q + sub0 + sub1
// ============================================================
__global__ __launch_bounds__(256, 2) void k_scores(const float* __restrict__ C,
                                                   const float* __restrict__ Q,
                                                   const float* __restrict__ w4mlu) {
    __shared__ float Cs[32][128];
    __shared__ float Qs[32][128];
    int b = blockIdx.z;
    int cbase = blockIdx.y * 128;
    int qbase = blockIdx.x * 128;
    const float* Cb = C + (size_t)b * DD * LC + cbase;
    const float* Qb = Q + (size_t)b * DD * LQ + qbase;
    int tid = threadIdx.x;
    int tx = tid & 15, ty = tid >> 4;

    unsigned long long acc2[4][8];
    #pragma unroll
    for (int p = 0; p < 4; p++)
        #pragma unroll
        for (int j = 0; j < 8; j++) acc2[p][j] = 0ull;

    for (int k0 = 0; k0 < DD; k0 += 32) {
        #pragma unroll
        for (int p = 0; p < 4; p++) {
            int r  = (tid >> 5) + p * 8;
            int c4 = (tid & 31) * 4;
            float w = w4mlu[k0 + r];
            float4 cv = *(const float4*)(Cb + (size_t)(k0 + r) * LC + c4);
            cv.x *= w; cv.y *= w; cv.z *= w; cv.w *= w;
            *(float4*)&Cs[r][c4] = cv;
            float4 qv = *(const float4*)(Qb + (size_t)(k0 + r) * LQ + c4);
            *(float4*)&Qs[r][c4] = qv;
        }
        __syncthreads();
        MK_INNER(Cs, Qs)
        __syncthreads();
    }
    MK_UNPACK()

    float s1v[8];
    #pragma unroll
    for (int j = 0; j < 8; j++) {
        int cc = (j < 4) ? tx * 4 + j : 64 + tx * 4 + (j - 4);
        s1v[j] = g_sub1[b * LQ + qbase + cc];
    }
    float* Sout = g_S + ((size_t)b * LC + cbase) * LQ + qbase;
    #pragma unroll
    for (int i = 0; i < 8; i++) {
        int r = (i < 4) ? ty * 4 + i : 64 + ty * 4 + (i - 4);
        float s0 = g_sub0[b * LC + cbase + r];
        float4 o0, o1;
        o0.x = accf[i][0] + s0 + s1v[0];
        o0.y = accf[i][1] + s0 + s1v[1];
        o0.z = accf[i][2] + s0 + s1v[2];
        o0.w = accf[i][3] + s0 + s1v[3];
        o1.x = accf[i][4] + s0 + s1v[4];
        o1.y = accf[i][5] + s0 + s1v[5];
        o1.z = accf[i][6] + s0 + s1v[6];
        o1.w = accf[i][7] + s0 + s1v[7];
        *(float4*)(Sout + (size_t)r * LQ + tx * 4)      = o0;
        *(float4*)(Sout + (size_t)r * LQ + 64 + tx * 4) = o1;
    }
}

// ============================================================
// K2a: softmax-over-q stats (one warp per (b,c) row)
// ============================================================
__global__ void k_rowstats(const int* __restrict__ Qmask) {
    int w = blockIdx.x * 8 + (threadIdx.x >> 5);
    int lane = threadIdx.x & 31;
    if (w >= BB * LC) return;
    int b = w / LC;
    const float* Sp = g_S + (size_t)w * LQ;
    const int* qm = Qmask + b * LQ;
    float vals[16];
    float m = -INFINITY;
    #pragma unroll
    for (int i = 0; i < 16; i++) {
        int q = lane + 32 * i;
        float v = Sp[q];
        if (!qm[q]) v += NEGF;
        vals[i] = v;
        m = fmaxf(m, v);
    }
    #pragma unroll
    for (int o = 16; o > 0; o >>= 1) m = fmaxf(m, __shfl_xor_sync(0xffffffffu, m, o));
    float s = 0.f;
    #pragma unroll
    for (int i = 0; i < 16; i++) s += __expf(vals[i] - m);
    #pragma unroll
    for (int o = 16; o > 0; o >>= 1) s += __shfl_xor_sync(0xffffffffu, s, o);
    if (lane == 0) { g_rmax[w] = m; g_rinv[w] = 1.f / s; }
}

// ============================================================
// K2b: softmax-over-c partial stats (c split into 4 chunks, MLP=4)
// ============================================================
__global__ void k_colstats_part(const int* __restrict__ Cmask) {
    __shared__ float sm[8][33], ss[8][33];
    __shared__ float cadd[512];
    int b = blockIdx.z;
    int chunk = blockIdx.y * 512;
    int lane = threadIdx.x & 31;
    int yg = threadIdx.x >> 5;
    for (int i = threadIdx.x; i < 512; i += 256)
        cadd[i] = Cmask[b * LC + chunk + i] ? 0.f : NEGF;
    __syncthreads();
    int q = blockIdx.x * 32 + lane;
    int cloc = yg * 64;
    const float* Sp = g_S + (size_t)b * LC * LQ + (size_t)(chunk + cloc) * LQ + q;
    float m = -INFINITY, s = 0.f;
    #pragma unroll 4
    for (int i = 0; i < 16; i++) {
        const float* p = Sp + (size_t)i * 4 * LQ;
        float v0 = p[0]          + cadd[cloc + i * 4 + 0];
        float v1 = p[LQ]         + cadd[cloc + i * 4 + 1];
        float v2 = p[2 * LQ]     + cadd[cloc + i * 4 + 2];
        float v3 = p[3 * LQ]     + cadd[cloc + i * 4 + 3];
        float m4 = fmaxf(fmaxf(v0, v1), fmaxf(v2, v3));
        float mn = fmaxf(m, m4);
        s = s * __expf(m - mn) + __expf(v0 - mn) + __expf(v1 - mn)
                               + __expf(v2 - mn) + __expf(v3 - mn);
        m = mn;
    }
    sm[yg][lane] = m; ss[yg][lane] = s;
    __syncthreads();
    if (yg == 0) {
        float M = m, S = s;
        #pragma unroll
        for (int g = 1; g < 8; g++) {
            float m2 = sm[g][lane], s2 = ss[g][lane];
            float mn = fmaxf(M, m2);
            S = S * __expf(M - mn) + s2 * __expf(m2 - mn);
            M = mn;
        }
        int idx = (blockIdx.y * BB + b) * LQ + q;
        g_cpm[idx] = M;
        g_cps[idx] = S;
    }
}

__global__ void k_colstats_merge() {
    int t = blockIdx.x * 256 + threadIdx.x;
    if (t >= BB * LQ) return;
    float M = -INFINITY, S = 0.f;
    #pragma unroll
    for (int g = 0; g < 4; g++) {
        float m2 = g_cpm[g * BB * LQ + t], s2 = g_cps[g * BB * LQ + t];
        float mn = fmaxf(M, m2);
        S = S * __expf(M - mn) + s2 * __expf(m2 - mn);
        M = mn;
    }
    g_cmax[t] = M;
    g_cinv[t] = 1.f / S;
}

// ============================================================
// K3: A = S1 @ Qt
// ============================================================
__global__ __launch_bounds__(256, 2) void k_gemmA(const float* __restrict__ Q,
                                                  const int* __restrict__ Qmask) {
    __shared__ float Ss[32][132];
    __shared__ float Qs[32][132];
    __shared__ float rmaxs[128], rinvs[128];
    __shared__ float qmadd[LQ];
    int b = blockIdx.y;
    int cbase = blockIdx.x * 128;
    int tid = threadIdx.x;
    if (tid < 128) {
        rmaxs[tid] = g_rmax[b * LC + cbase + tid];
        rinvs[tid] = g_rinv[b * LC + cbase + tid];
    }
    for (int i = tid; i < LQ; i += 256) qmadd[i] = Qmask[b * LQ + i] ? 0.f : NEGF;
    __syncthreads();
    int tx = tid & 15, ty = tid >> 4;
    unsigned long long acc2[4][8];
    #pragma unroll
    for (int p = 0; p < 4; p++)
        #pragma unroll
        for (int j = 0; j < 8; j++) acc2[p][j] = 0ull;

    const float* Qb = Q + (size_t)b * DD * LQ;
    const float* Sb = g_S + ((size_t)b * LC + cbase) * LQ;

    for (int k0 = 0; k0 < LQ; k0 += 32) {
        #pragma unroll
        for (int p = 0; p < 4; p++) {
            int row = (tid >> 3) + p * 32;
            int qq  = (tid & 7) * 4;
            float4 v = *(const float4*)(Sb + (size_t)row * LQ + k0 + qq);
            float rm = rmaxs[row], ri = rinvs[row];
            Ss[qq + 0][row] = __expf(v.x + qmadd[k0 + qq + 0] - rm) * ri;
            Ss[qq + 1][row] = __expf(v.y + qmadd[k0 + qq + 1] - rm) * ri;
            Ss[qq + 2][row] = __expf(v.z + qmadd[k0 + qq + 2] - rm) * ri;
            Ss[qq + 3][row] = __expf(v.w + qmadd[k0 + qq + 3] - rm) * ri;
            float4 w = *(const float4*)(Qb + (size_t)row * LQ + k0 + qq);
            Qs[qq + 0][row] = w.x; Qs[qq + 1][row] = w.y;
            Qs[qq + 2][row] = w.z; Qs[qq + 3][row] = w.w;
        }
        __syncthreads();
        MK_INNER(Ss, Qs)
        __syncthreads();
    }
    MK_UNPACK()

    float* Ab = g_A + ((size_t)b * LC + cbase) * DD;
    #pragma unroll
    for (int i = 0; i < 8; i++) {
        int r = (i < 4) ? ty * 4 + i : 64 + ty * 4 + (i - 4);
        float4 o0 = make_float4(accf[i][0], accf[i][1], accf[i][2], accf[i][3]);
        float4 o1 = make_float4(accf[i][4], accf[i][5], accf[i][6], accf[i][7]);
        *(float4*)(Ab + (size_t)r * DD + tx * 4)      = o0;
        *(float4*)(Ab + (size_t)r * DD + 64 + tx * 4) = o1;
    }
}

// ============================================================
// K4: V2 partials: V2[b,q,d] = sum_c S2[c,q]*C[b,d,c]
// ============================================================
__global__ __launch_bounds__(256, 2) void k_gemmV2(const float* __restrict__ C,
                                                   const int* __restrict__ Cmask) {
    __shared__ float Ss[32][132];
    __shared__ float Cs[32][132];
    __shared__ float cmaxs[128], cinvs[128];
    __shared__ float cmadd[512];
    int b = blockIdx.z;
    int qbase = blockIdx.x * 128;
    int c0chunk = blockIdx.y * 512;
    int tid = threadIdx.x;
    if (tid < 128) {
        cmaxs[tid] = g_cmax[b * LQ + qbase + tid];
        cinvs[tid] = g_cinv[b * LQ + qbase + tid];
    }
    for (int i = tid; i < 512; i += 256) cmadd[i] = Cmask[b * LC + c0chunk + i] ? 0.f : NEGF;
    __syncthreads();
    int tx = tid & 15, ty = tid >> 4;
    unsigned long long acc2[4][8];
    #pragma unroll
    for (int p = 0; p < 4; p++)
        #pragma unroll
        for (int j = 0; j < 8; j++) acc2[p][j] = 0ull;

    const float* Cb = C + (size_t)b * DD * LC;
    const float* Sb = g_S + ((size_t)b * LC + c0chunk) * LQ + qbase;

    for (int k0 = 0; k0 < 512; k0 += 32) {
        #pragma unroll
        for (int p = 0; p < 4; p++) {
            int kk = (tid >> 5) + p * 8;
            int q4 = (tid & 31) * 4;
            float4 v = *(const float4*)(Sb + (size_t)(k0 + kk) * LQ + q4);
            float ca = cmadd[k0 + kk];
            float4 e;
            e.x = __expf(v.x + ca - cmaxs[q4 + 0]) * cinvs[q4 + 0];
            e.y = __expf(v.y + ca - cmaxs[q4 + 1]) * cinvs[q4 + 1];
            e.z = __expf(v.z + ca - cmaxs[q4 + 2]) * cinvs[q4 + 2];
            e.w = __expf(v.w + ca - cmaxs[q4 + 3]) * cinvs[q4 + 3];
            *(float4*)&Ss[kk][q4] = e;
            int drow = (tid >> 3) + p * 32;
            int cc   = (tid & 7) * 4;
            float4 w = *(const float4*)(Cb + (size_t)drow * LC + c0chunk + k0 + cc);
            Cs[cc + 0][drow] = w.x; Cs[cc + 1][drow] = w.y;
            Cs[cc + 2][drow] = w.z; Cs[cc + 3][drow] = w.w;
        }
        __syncthreads();
        MK_INNER(Ss, Cs)
        __syncthreads();
    }
    MK_UNPACK()

    float* Vp = g_V2p + ((size_t)blockIdx.y * BB * LQ + (size_t)b * LQ + qbase) * DD;
    #pragma unroll
    for (int i = 0; i < 8; i++) {
        int r = (i < 4) ? ty * 4 + i : 64 + ty * 4 + (i - 4);
        float4 o0 = make_float4(accf[i][0], accf[i][1], accf[i][2], accf[i][3]);
        float4 o1 = make_float4(accf[i][4], accf[i][5], accf[i][6], accf[i][7]);
        *(float4*)(Vp + (size_t)r * DD + tx * 4)      = o0;
        *(float4*)(Vp + (size_t)r * DD + 64 + tx * 4) = o1;
    }
}

__global__ void k_reduceV2() {
    const int n = BB * LQ * DD / 4;
    int i = blockIdx.x * blockDim.x + threadIdx.x;
    if (i < n) {
        const float4* p = (const float4*)g_V2p;
        float4 a = p[i], b2 = p[i + n], c = p[i + 2 * n], d = p[i + 3 * n];
        float4 o;
        o.x = a.x + b2.x + c.x + d.x;
        o.y = a.y + b2.y + c.y + d.y;
        o.z = a.z + b2.z + c.z + d.z;
        o.w = a.w + b2.w + c.w + d.w;
        ((float4*)g_V2)[i] = o;
    }
}

// ============================================================
// K5: Bmat = S1 @ V2
// ============================================================
__global__ __launch_bounds__(256, 2) void k_gemmB(const int* __restrict__ Qmask) {
    __shared__ float Ss[32][132];
    __shared__ float Vs[32][132];
    __shared__ float rmaxs[128], rinvs[128];
    __shared__ float qmadd[LQ];
    int b = blockIdx.y;
    int cbase = blockIdx.x * 128;
    int tid = threadIdx.x;
    if (tid < 128) {
        rmaxs[tid] = g_rmax[b * LC + cbase + tid];
        rinvs[tid] = g_rinv[b * LC + cbase + tid];
    }
    for (int i = tid; i < LQ; i += 256) qmadd[i] = Qmask[b * LQ + i] ? 0.f : NEGF;
    __syncthreads();
    int tx = tid & 15, ty = tid >> 4;
    unsigned long long acc2[4][8];
    #pragma unroll
    for (int p = 0; p < 4; p++)
        #pragma unroll
        for (int j = 0; j < 8; j++) acc2[p][j] = 0ull;

    const float* Sb = g_S + ((size_t)b * LC + cbase) * LQ;
    const float* Vb = g_V2 + (size_t)b * LQ * DD;

    for (int k0 = 0; k0 < LQ; k0 += 32) {
        #pragma unroll
        for (int p = 0; p < 4; p++) {
            int row = (tid >> 3) + p * 32;
            int qq  = (tid & 7) * 4;
            float4 v = *(const float4*)(Sb + (size_t)row * LQ + k0 + qq);
            float rm = rmaxs[row], ri = rinvs[row];
            Ss[qq + 0][row] = __expf(v.x + qmadd[k0 + qq + 0] - rm) * ri;
            Ss[qq + 1][row] = __expf(v.y + qmadd[k0 + qq + 1] - rm) * ri;
            Ss[qq + 2][row] = __expf(v.z + qmadd[k0 + qq + 2] - rm) * ri;
            Ss[qq + 3][row] = __expf(v.w + qmadd[k0 + qq + 3] - rm) * ri;
            int kk = (tid >> 5) + p * 8;
            int d4 = (tid & 31) * 4;
            float4 w = *(const float4*)(Vb + (size_t)(k0 + kk) * DD + d4);
            *(float4*)&Vs[kk][d4] = w;
        }
        __syncthreads();
        MK_INNER(Ss, Vs)
        __syncthreads();
    }
    MK_UNPACK()

    float* Bmb = g_Bm + ((size_t)b * LC + cbase) * DD;
    #pragma unroll
    for (int i = 0; i < 8; i++) {
        int r = (i < 4) ? ty * 4 + i : 64 + ty * 4 + (i - 4);
        float4 o0 = make_float4(accf[i][0], accf[i][1], accf[i][2], accf[i][3]);
        float4 o1 = make_float4(accf[i][4], accf[i][5], accf[i][6], accf[i][7]);
        *(float4*)(Bmb + (size_t)r * DD + tx * 4)      = o0;
        *(float4*)(Bmb + (size_t)r * DD + 64 + tx * 4) = o1;
    }
}

// ============================================================
// K6: assemble out[b, 4D, Lc]
// ============================================================
__global__ void k_assemble(const float* __restrict__ C, float* __restrict__ out) {
    __shared__ float As[32][33], Bs[32][33];
    int b = blockIdx.z;
    int cbase = blockIdx.x * 32;
    int dbase = blockIdx.y * 32;
    int x = threadIdx.x, y = threadIdx.y;
    #pragma unroll
    for (int yy = 0; yy < 4; yy++) {
        int c = y + 8 * yy;
        As[c][x] = g_A[((size_t)b * LC + cbase + c) * DD + dbase + x];
        Bs[c][x] = g_Bm[((size_t)b * LC + cbase + c) * DD + dbase + x];
    }
    __syncthreads();
    #pragma unroll
    for (int yy = 0; yy < 4; yy++) {
        int d = y + 8 * yy;
        float cv = C[((size_t)b * DD + dbase + d) * LC + cbase + x];
        float av = As[x][d];
        float bv = Bs[x][d];
        size_t obase = (size_t)b * 4 * DD * LC + cbase + x;
        out[obase + (size_t)(dbase + d) * LC]            = cv;
        out[obase + (size_t)(DD + dbase + d) * LC]       = av;
        out[obase + (size_t)(2 * DD + dbase + d) * LC]   = cv * av;
        out[obase + (size_t)(3 * DD + dbase + d) * LC]   = cv * bv;
    }
}

// ============================================================
extern "C" void kernel_launch(void* const* d_in, const int* in_sizes, int n_in,
                              void* d_out, int out_size) {
    const float* C     = (const float*)d_in[0];
    const float* Q     = (const float*)d_in[1];
    const int*   Cmask = (const int*)d_in[2];
    const int*   Qmask = (const int*)d_in[3];
    const float* w4C   = (const float*)d_in[4];
    const float* w4Q   = (const float*)d_in[5];
    const float* w4mlu = (const float*)d_in[6];
    const float* bias  = (const float*)d_in[7];
    float* out = (float*)d_out;

    int nsub = BB * LC + BB * LQ;
    k_sub<<<(nsub + 255) / 256, 256>>>(C, Q, w4C, w4Q, bias);
    k_scores<<<dim3(4, 16, 16), 256>>>(C, Q, w4mlu);
    k_rowstats<<<(BB * LC) / 8, 256>>>(Qmask);
    k_colstats_part<<<dim3(16, 4, 16), 256>>>(Cmask);
    k_colstats_merge<<<32, 256>>>();
    k_gemmA<<<dim3(16, 16), 256>>>(Q, Qmask);
    k_gemmV2<<<dim3(4, 4, 16), 256>>>(C, Cmask);
    k_reduceV2<<<(BB * LQ * DD / 4 + 255) / 256, 256>>>();
    k_gemmB<<<dim3(16, 16), 256>>>(Qmask);
    k_assemble<<<dim3(64, 4, 16), dim3(32, 8)>>>(C, out);
}